// round 1
// baseline (speedup 1.0000x reference)
#include <cuda_runtime.h>
#include <cuda_bf16.h>

// Problem dims
#define PB   64
#define PNC  5
#define PL   20
#define PF   20
#define PC   8192
#define PE   300
#define PH   512
#define PBN  320            // B*NC
#define G4H  2048           // 4*H

// Scratch strides (padded to multiples of 128 rows)
#define SS   (384*512)      // state buffer rows*H
#define PS   (384L*2048)    // partial buffer stride

// -------- device scratch (no allocation allowed) --------
__device__ float g_Xv1[1280L*2048];     // [F*B, 4H] precomputed x@Wih_v1^T + b
__device__ float g_Xt1[6400L*2048];     // [L*BN, 4H] precomputed emb@Wih_t1^T + b
__device__ float g_part[4*PS];          // split-K partials
__device__ float g_h1[2*SS];
__device__ float g_c1[2*SS];
__device__ float g_h2[2*SS];
__device__ float g_c2[2*SS];
__device__ float g_nh1[SS];
__device__ float g_nc1[SS];
__device__ float g_fe[384*1024];

// ---------------- generic fp32 SGEMM ----------------
// out[m, n] = sum_k A(m, kOff+k) * W[n, kOff+k]  (+ bias[n])
// A-gather modes:
//  0: direct,   A[r*lda + k]
//  1: video,    r = f*64+b -> vf[(b*20+f)*8192 + k]
//  2: embed,    r = l*320+q -> embed[questions[q*20+l]*300 + k]
//  3: concat,   k<512 ? A[r*512+k] : A2[r*512+k-512]
template<int AM>
__device__ __forceinline__ float loadA(const float* __restrict__ A,
                                       const float* __restrict__ A2,
                                       int r, int k, int M, int Kfull, int lda,
                                       const int* __restrict__ ques,
                                       const float* __restrict__ emb)
{
    if (r >= M || k >= Kfull) return 0.f;
    if (AM == 0) return A[(long)r * lda + k];
    if (AM == 1) { int f = r >> 6, b = r & 63; return A[(long)(b*20 + f)*8192 + k]; }
    if (AM == 2) { int l = r / 320, q = r - l*320; int tok = ques[q*20 + l];
                   return emb[(long)tok*300 + k]; }
    if (AM == 3) return (k < 512) ? A[(long)r*512 + k] : A2[(long)r*512 + (k-512)];
    return 0.f;
}

template<int AM>
__global__ __launch_bounds__(256)
void sgemm_k(const float* __restrict__ A, const float* __restrict__ A2,
             const float* __restrict__ W, const float* __restrict__ bias,
             float* __restrict__ out, int outStride, long partStride,
             int M, int Kfull, int lda, int Ktile, int Mstore,
             const int* __restrict__ ques, const float* __restrict__ emb)
{
    __shared__ float As[8][128];
    __shared__ float Bs[8][128];

    const int m0 = blockIdx.y * 128;
    const int n0 = blockIdx.x * 128;
    const int kOff = blockIdx.z * Ktile;
    out += (long)blockIdx.z * partStride;

    const int tid = threadIdx.x;
    const int aRow = tid >> 1;          // 0..127
    const int aK   = (tid & 1) * 4;     // 0 or 4
    const int tx = tid & 15;
    const int ty = tid >> 4;

    float acc[8][8];
#pragma unroll
    for (int i = 0; i < 8; i++)
#pragma unroll
        for (int j = 0; j < 8; j++) acc[i][j] = 0.f;

    const int nk = (Ktile + 7) / 8;
    for (int kt = 0; kt < nk; kt++) {
        const int kbase = kOff + kt * 8;
#pragma unroll
        for (int i = 0; i < 4; i++) {
            int k = kbase + aK + i;
            As[aK + i][aRow] = loadA<AM>(A, A2, m0 + aRow, k, M, Kfull, lda, ques, emb);
            int n = n0 + aRow;
            Bs[aK + i][aRow] = (k < Kfull) ? W[(long)n * Kfull + k] : 0.f;
        }
        __syncthreads();
#pragma unroll
        for (int kk = 0; kk < 8; kk++) {
            float a[8], b[8];
#pragma unroll
            for (int i = 0; i < 8; i++) a[i] = As[kk][ty*8 + i];
#pragma unroll
            for (int j = 0; j < 8; j++) b[j] = Bs[kk][tx*8 + j];
#pragma unroll
            for (int i = 0; i < 8; i++)
#pragma unroll
                for (int j = 0; j < 8; j++) acc[i][j] += a[i] * b[j];
        }
        __syncthreads();
    }

#pragma unroll
    for (int i = 0; i < 8; i++) {
        int m = m0 + ty*8 + i;
        if (m < Mstore) {
            long ro = (long)m * outStride + n0 + tx*8;
#pragma unroll
            for (int j = 0; j < 8; j++) {
                float v = acc[i][j];
                if (bias) v += bias[n0 + tx*8 + j];
                out[ro + j] = v;
            }
        }
    }
}

// ---------------- LSTM pointwise ----------------
__device__ __forceinline__ float sigf(float x) { return 1.f / (1.f + expf(-x)); }

__global__ void pw_cell(const float* __restrict__ xpre, const float* __restrict__ bias,
                        const float* __restrict__ part, long ps, int np,
                        const float* __restrict__ c_in,
                        float* __restrict__ h_out, float* __restrict__ c_out, int M)
{
    int idx = blockIdx.x * blockDim.x + threadIdx.x;
    if (idx >= M * 512) return;
    int m = idx >> 9, j = idx & 511;
    long base = (long)m * 2048;
    float g[4];
#pragma unroll
    for (int gi = 0; gi < 4; gi++) {
        int c = gi * 512 + j;
        float s = bias ? bias[c] : 0.f;
        if (xpre) s += xpre[base + c];
        for (int z = 0; z < np; z++) s += part[z * ps + base + c];
        g[gi] = s;
    }
    float i = sigf(g[0]), f = sigf(g[1]), gg = tanhf(g[2]), o = sigf(g[3]);
    float cn = f * c_in[idx] + i * gg;
    c_out[idx] = cn;
    h_out[idx] = o * tanhf(cn);
}

__global__ void pw_cell2_mask(const float* __restrict__ bias,
                              const float* __restrict__ part, long ps, int np,
                              const float* __restrict__ c2_in,
                              const float* __restrict__ nh1, const float* __restrict__ nc1,
                              const float* __restrict__ h1_in, const float* __restrict__ c1_in,
                              const float* __restrict__ h2_in,
                              float* __restrict__ h1_o, float* __restrict__ c1_o,
                              float* __restrict__ h2_o, float* __restrict__ c2_o,
                              const int* __restrict__ qlen, int t)
{
    int idx = blockIdx.x * blockDim.x + threadIdx.x;
    if (idx >= 320 * 512) return;
    int m = idx >> 9, j = idx & 511;
    long base = (long)m * 2048;
    float g[4];
#pragma unroll
    for (int gi = 0; gi < 4; gi++) {
        int c = gi * 512 + j;
        float s = bias ? bias[c] : 0.f;
        for (int z = 0; z < np; z++) s += part[z * ps + base + c];
        g[gi] = s;
    }
    float i = sigf(g[0]), f = sigf(g[1]), gg = tanhf(g[2]), o = sigf(g[3]);
    float cn = f * c2_in[idx] + i * gg;
    float hn = o * tanhf(cn);
    bool upd = t < qlen[m / 5];
    h1_o[idx] = upd ? nh1[idx] : h1_in[idx];
    c1_o[idx] = upd ? nc1[idx] : c1_in[idx];
    h2_o[idx] = upd ? hn : h2_in[idx];
    c2_o[idx] = upd ? cn : c2_in[idx];
}

// broadcast video-final states [64,512] -> text-init [320,512]
__global__ void bc_init(const float* __restrict__ sh1, const float* __restrict__ sc1,
                        const float* __restrict__ sh2, const float* __restrict__ sc2,
                        float* __restrict__ dh1, float* __restrict__ dc1,
                        float* __restrict__ dh2, float* __restrict__ dc2)
{
    int idx = blockIdx.x * blockDim.x + threadIdx.x;
    if (idx >= 320 * 512) return;
    int q = idx >> 9, j = idx & 511;
    int s = (q / 5) * 512 + j;
    dh1[idx] = sh1[s]; dc1[idx] = sc1[s];
    dh2[idx] = sh2[s]; dc2[idx] = sc2[s];
}

// outputs[m] = fe[m,:] . dec2_w + dec2_b   (one warp per m)
__global__ void dec2_k(const float* __restrict__ fe, const float* __restrict__ w,
                       const float* __restrict__ b, float* __restrict__ out)
{
    int warp = (blockIdx.x * blockDim.x + threadIdx.x) >> 5;
    int lane = threadIdx.x & 31;
    if (warp >= 320) return;
    float s = 0.f;
    for (int k = lane; k < 1024; k += 32) s += fe[(long)warp * 1024 + k] * w[k];
#pragma unroll
    for (int o = 16; o; o >>= 1) s += __shfl_xor_sync(0xFFFFFFFFu, s, o);
    if (lane == 0) out[warp] = s + b[0];
}

__global__ void argmax_k(const float* __restrict__ outv, float* __restrict__ pred)
{
    int b = threadIdx.x;
    if (b < 64) {
        float best = outv[b * 5]; int bi = 0;
#pragma unroll
        for (int n = 1; n < 5; n++) {
            float v = outv[b * 5 + n];
            if (v > best) { best = v; bi = n; }
        }
        pred[b] = (float)bi;
    }
}

// ---------------- host orchestration ----------------
extern "C" void kernel_launch(void* const* d_in, const int* in_sizes, int n_in,
                              void* d_out, int out_size)
{
    const float* vf      = (const float*)d_in[0];
    const int*   ques    = (const int*)  d_in[1];
    const int*   qlen    = (const int*)  d_in[2];
    const float* embed   = (const float*)d_in[3];
    const float* Wih_t1  = (const float*)d_in[4];
    const float* Whh_t1  = (const float*)d_in[5];
    const float* b_t1    = (const float*)d_in[6];
    const float* Wih_t2  = (const float*)d_in[7];
    const float* Whh_t2  = (const float*)d_in[8];
    const float* b_t2    = (const float*)d_in[9];
    const float* Wih_v1  = (const float*)d_in[10];
    const float* Whh_v1  = (const float*)d_in[11];
    const float* b_v1    = (const float*)d_in[12];
    const float* Wih_v2  = (const float*)d_in[13];
    const float* Whh_v2  = (const float*)d_in[14];
    const float* b_v2    = (const float*)d_in[15];
    const float* dec1_w  = (const float*)d_in[16];
    const float* dec1_b  = (const float*)d_in[17];
    const float* dec2_w  = (const float*)d_in[18];
    const float* dec2_b  = (const float*)d_in[19];
    float* out = (float*)d_out;

    float *Xv1, *Xt1, *part, *h1, *c1, *h2, *c2, *nh1, *nc1, *fe;
    cudaGetSymbolAddress((void**)&Xv1,  g_Xv1);
    cudaGetSymbolAddress((void**)&Xt1,  g_Xt1);
    cudaGetSymbolAddress((void**)&part, g_part);
    cudaGetSymbolAddress((void**)&h1,   g_h1);
    cudaGetSymbolAddress((void**)&c1,   g_c1);
    cudaGetSymbolAddress((void**)&h2,   g_h2);
    cudaGetSymbolAddress((void**)&c2,   g_c2);
    cudaGetSymbolAddress((void**)&nh1,  g_nh1);
    cudaGetSymbolAddress((void**)&nc1,  g_nc1);
    cudaGetSymbolAddress((void**)&fe,   g_fe);

    const dim3 blk(256);

    // zero initial states (ping 0)
    cudaMemsetAsync(h1, 0, SS * sizeof(float));
    cudaMemsetAsync(c1, 0, SS * sizeof(float));
    cudaMemsetAsync(h2, 0, SS * sizeof(float));
    cudaMemsetAsync(c2, 0, SS * sizeof(float));

    // Xv1 = vf @ Wih_v1^T + b_v1   [1280, 2048], K=8192
    sgemm_k<1><<<dim3(16, 10, 1), blk>>>(vf, nullptr, Wih_v1, b_v1, Xv1, 2048, 0,
                                         1280, 8192, 0, 8192, 1280, nullptr, nullptr);
    // Xt1 = emb @ Wih_t1^T + b_t1  [6400, 2048], K=300 (Ktile padded to 304)
    sgemm_k<2><<<dim3(16, 50, 1), blk>>>(nullptr, nullptr, Wih_t1, b_t1, Xt1, 2048, 0,
                                         6400, 300, 0, 304, 6400, ques, embed);

    // ---- video recurrence ----
    int p = 0;
    for (int t = 0; t < PF; t++) {
        int q = p ^ 1;
        // cell1: gates1 = Xv1[t] + h1 @ Whh_v1^T   (split-K=4)
        sgemm_k<0><<<dim3(16, 1, 4), blk>>>(h1 + p*SS, nullptr, Whh_v1, nullptr,
                                            part, 2048, PS, 64, 512, 512, 128, 384,
                                            nullptr, nullptr);
        pw_cell<<<128, 256>>>(Xv1 + (long)t*64*2048, nullptr, part, PS, 4,
                              c1 + p*SS, h1 + q*SS, c1 + q*SS, 64);
        // cell2: gates2 = h1_new @ Wih_v2^T + h2 @ Whh_v2^T + b_v2  (2x split-K=2)
        sgemm_k<0><<<dim3(16, 1, 2), blk>>>(h1 + q*SS, nullptr, Wih_v2, nullptr,
                                            part, 2048, PS, 64, 512, 512, 256, 384,
                                            nullptr, nullptr);
        sgemm_k<0><<<dim3(16, 1, 2), blk>>>(h2 + p*SS, nullptr, Whh_v2, nullptr,
                                            part + 2*PS, 2048, PS, 64, 512, 512, 256, 384,
                                            nullptr, nullptr);
        pw_cell<<<128, 256>>>(nullptr, b_v2, part, PS, 4,
                              c2 + p*SS, h2 + q*SS, c2 + q*SS, 64);
        p = q;
    }

    // broadcast video-final states to text init (write to the other ping)
    int tp = p ^ 1;
    bc_init<<<640, 256>>>(h1 + p*SS, c1 + p*SS, h2 + p*SS, c2 + p*SS,
                          h1 + tp*SS, c1 + tp*SS, h2 + tp*SS, c2 + tp*SS);
    p = tp;

    // ---- text recurrence (masked) ----
    for (int t = 0; t < PL; t++) {
        int q = p ^ 1;
        // cell1 candidate: gates = Xt1[t] + h1 @ Whh_t1^T  (split-K=2)
        sgemm_k<0><<<dim3(16, 3, 2), blk>>>(h1 + p*SS, nullptr, Whh_t1, nullptr,
                                            part, 2048, PS, 320, 512, 512, 256, 384,
                                            nullptr, nullptr);
        pw_cell<<<640, 256>>>(Xt1 + (long)t*320*2048, nullptr, part, PS, 2,
                              c1 + p*SS, nh1, nc1, 320);
        // cell2: gates = nh1 @ Wih_t2^T + h2 @ Whh_t2^T + b_t2
        sgemm_k<0><<<dim3(16, 3, 2), blk>>>(nh1, nullptr, Wih_t2, nullptr,
                                            part, 2048, PS, 320, 512, 512, 256, 384,
                                            nullptr, nullptr);
        sgemm_k<0><<<dim3(16, 3, 2), blk>>>(h2 + p*SS, nullptr, Whh_t2, nullptr,
                                            part + 2*PS, 2048, PS, 320, 512, 512, 256, 384,
                                            nullptr, nullptr);
        pw_cell2_mask<<<640, 256>>>(b_t2, part, PS, 4, c2 + p*SS, nh1, nc1,
                                    h1 + p*SS, c1 + p*SS, h2 + p*SS,
                                    h1 + q*SS, c1 + q*SS, h2 + q*SS, c2 + q*SS,
                                    qlen, t);
        p = q;
    }

    // ---- decoder ----
    // fe = [h1, h2] @ dec1_w^T + dec1_b   [320, 1024], K=1024
    sgemm_k<3><<<dim3(8, 3, 1), blk>>>(h1 + p*SS, h2 + p*SS, dec1_w, dec1_b,
                                       fe, 1024, 0, 320, 1024, 512, 1024, 384,
                                       nullptr, nullptr);
    dec2_k<<<10, 1024>>>(fe, dec2_w, dec2_b, out);
    if (out_size >= 384)
        argmax_k<<<1, 64>>>(out, out + 320);
}

// round 2
// speedup vs baseline: 1.0313x; 1.0313x over previous
#include <cuda_runtime.h>
#include <cuda_bf16.h>

typedef unsigned long long ull;

// Problem dims
#define PH   512
#define SS   (320*512)      // state buffer (rows*H)

// -------- device scratch (no allocation allowed) --------
__device__ float g_Xv1[1280L*2048];     // [B*F, 4H] rows (b*20+f): vf@Wih_v1^T + b_v1
__device__ float g_Xt1[6400L*2048];     // [L*BN, 4H]: emb@Wih_t1^T + b_t1
__device__ float g_h1[2*SS];
__device__ float g_c1[2*SS];
__device__ float g_h2[2*SS];
__device__ float g_c2[2*SS];
__device__ float g_nh1[SS];
__device__ float g_nc1[SS];
__device__ float g_fe[320*1024];

// ---- packed f32x2 helpers ----
__device__ __forceinline__ ull pk2(float lo, float hi) {
    ull r;
    asm("mov.b64 %0, {%1, %2};" : "=l"(r) : "f"(lo), "f"(hi));
    return r;
}
__device__ __forceinline__ void upk2(ull v, float& lo, float& hi) {
    asm("mov.b64 {%0, %1}, %2;" : "=f"(lo), "=f"(hi) : "l"(v));
}
#define FMA2(acc, a, b) asm("fma.rn.f32x2 %0, %1, %2, %3;" : "=l"(acc) : "l"(a), "l"(b), "l"(acc))

__device__ __forceinline__ float sigf(float x) { return 1.f / (1.f + expf(-x)); }

// =====================================================================
// Generic 128x128 fp32 GEMM (f32x2 inner, software-pipelined loads)
// out[m,n] = sum_k A(m,k) * W[n*Kfull+k] (+bias[n])
// AM: 0 = direct (float4), 2 = embedding gather, 3 = concat [A|A2] (lda=512)
// =====================================================================
template<int AM>
__global__ __launch_bounds__(256)
void sgemm2(const float* __restrict__ A, const float* __restrict__ A2,
            const float* __restrict__ W, const float* __restrict__ bias,
            float* __restrict__ out, int outStride,
            int M, int Kfull, int lda, int Mstore,
            const int* __restrict__ ques, const float* __restrict__ emb)
{
    __shared__ float As[8][128];
    __shared__ float Bs[8][128];

    const int tid = threadIdx.x;
    const int r   = tid >> 1;
    const int kq  = (tid & 1) * 4;
    const int m0  = blockIdx.y * 128;
    const int n0  = blockIdx.x * 128;
    const int tx  = tid & 15;
    const int ty  = tid >> 4;
    const int m   = m0 + r;
    const int n   = n0 + r;

    auto ldA = [&](int kb, float* p) {
        if (AM == 0) {
            const float4 v = *(const float4*)&A[(long)m * lda + kb + kq];
            p[0] = v.x; p[1] = v.y; p[2] = v.z; p[3] = v.w;
        } else if (AM == 2) {
            int l = m / 320, qq = m - l * 320;
            long tb = (long)ques[qq * 20 + l] * 300;
#pragma unroll
            for (int i = 0; i < 4; i++) {
                int k = kb + kq + i;
                p[i] = (k < Kfull) ? emb[tb + k] : 0.f;
            }
        } else {
#pragma unroll
            for (int i = 0; i < 4; i++) {
                int k = kb + kq + i;
                p[i] = (m < M) ? ((k < 512) ? A[(long)m * 512 + k]
                                            : A2[(long)m * 512 + (k - 512)]) : 0.f;
            }
        }
    };
    auto ldB = [&](int kb, float* p) {
        if (AM == 0) {
            const float4 v = *(const float4*)&W[(long)n * Kfull + kb + kq];
            p[0] = v.x; p[1] = v.y; p[2] = v.z; p[3] = v.w;
        } else {
#pragma unroll
            for (int i = 0; i < 4; i++) {
                int k = kb + kq + i;
                p[i] = (k < Kfull) ? W[(long)n * Kfull + k] : 0.f;
            }
        }
    };

    ull acc[8][4];
#pragma unroll
    for (int i = 0; i < 8; i++)
#pragma unroll
        for (int j = 0; j < 4; j++) acc[i][j] = 0ull;

    const int nk = (Kfull + 7) >> 3;
    float pa[4], pb[4];
    ldA(0, pa); ldB(0, pb);
#pragma unroll
    for (int z = 0; z < 4; z++) { As[kq + z][r] = pa[z]; Bs[kq + z][r] = pb[z]; }
    __syncthreads();

    for (int kt = 0; kt < nk; kt++) {
        const bool more = (kt + 1) < nk;
        if (more) { ldA((kt + 1) * 8, pa); ldB((kt + 1) * 8, pb); }
#pragma unroll
        for (int kk = 0; kk < 8; kk++) {
            const float4 a0 = *(const float4*)&As[kk][ty * 8];
            const float4 a1 = *(const float4*)&As[kk][ty * 8 + 4];
            const float4 b0 = *(const float4*)&Bs[kk][tx * 8];
            const float4 b1 = *(const float4*)&Bs[kk][tx * 8 + 4];
            ull bb[4] = { pk2(b0.x, b0.y), pk2(b0.z, b0.w),
                          pk2(b1.x, b1.y), pk2(b1.z, b1.w) };
            float av[8] = { a0.x, a0.y, a0.z, a0.w, a1.x, a1.y, a1.z, a1.w };
#pragma unroll
            for (int i = 0; i < 8; i++) {
                ull ad = pk2(av[i], av[i]);
#pragma unroll
                for (int j = 0; j < 4; j++) FMA2(acc[i][j], ad, bb[j]);
            }
        }
        __syncthreads();
        if (more) {
#pragma unroll
            for (int z = 0; z < 4; z++) { As[kq + z][r] = pa[z]; Bs[kq + z][r] = pb[z]; }
        }
        __syncthreads();
    }

#pragma unroll
    for (int i = 0; i < 8; i++) {
        int mm = m0 + ty * 8 + i;
        if (mm < Mstore) {
            long ro = (long)mm * outStride + n0 + tx * 8;
#pragma unroll
            for (int j = 0; j < 4; j++) {
                float lo, hi;
                upk2(acc[i][j], lo, hi);
                if (bias) { lo += bias[n0 + tx * 8 + 2 * j]; hi += bias[n0 + tx * 8 + 2 * j + 1]; }
                out[ro + 2 * j]     = lo;
                out[ro + 2 * j + 1] = hi;
            }
        }
    }
}

// =====================================================================
// Fused LSTM cell: gates GEMM (all 4 gates per (m,j)) + pointwise + mask
// gates[m, g*512+j] = sum_k Acat(m,k) * Wcat[g*512+j, k]  (+xpre)(+bias)
// TM=TY*RM rows, TJ=TX*RJ h-cols per block; 256 threads.
// =====================================================================
template<int TY, int TX, int RM, int RJ, int CC, int HX, int HB, int MK>
__global__ __launch_bounds__(256)
void cell_k(const float* __restrict__ A, const float* __restrict__ A2,
            const float* __restrict__ W, const float* __restrict__ W2,
            const float* __restrict__ bias,
            const float* __restrict__ xpre, int xstride,
            const float* __restrict__ c_in,
            float* __restrict__ h_out, float* __restrict__ c_out,
            const float* __restrict__ nc1,
            const float* __restrict__ h1_in, const float* __restrict__ c1_in,
            float* __restrict__ h1_o, float* __restrict__ c1_o,
            const int* __restrict__ qlen, int t)
{
    constexpr int TM = TY * RM;
    constexpr int TJ = TX * RJ;
    constexpr int K  = CC ? 1024 : 512;
    constexpr int NA = (TM * 8) / 256;
    constexpr int NB = (TJ * 32) / 256;

    __shared__ float As[8][TM];
    __shared__ float Bs[8][TJ * 4];

    const int tid = threadIdx.x;
    const int tx  = tid % TX;
    const int ty  = tid / TX;
    const int m0  = blockIdx.y * TM;
    const int j0  = blockIdx.x * TJ;

    auto ldA = [&](int kb, float* p) {
#pragma unroll
        for (int z = 0; z < NA; z++) {
            int i = tid + z * 256;
            int row = i >> 3, kk = i & 7, k = kb + kk, m = m0 + row;
            p[z] = CC ? ((k < 512) ? A[(long)m * 512 + k] : A2[(long)m * 512 + (k - 512)])
                      : A[(long)m * 512 + k];
        }
    };
    auto stA = [&](const float* p) {
#pragma unroll
        for (int z = 0; z < NA; z++) {
            int i = tid + z * 256;
            As[i & 7][i >> 3] = p[z];
        }
    };
    auto ldB = [&](int kb, float* p) {
#pragma unroll
        for (int z = 0; z < NB; z++) {
            int i = tid + z * 256;
            int col = i >> 3, kk = i & 7, k = kb + kk;
            int wr = (col & 3) * 512 + j0 + (col >> 2);
            p[z] = CC ? ((k < 512) ? W[(long)wr * 512 + k] : W2[(long)wr * 512 + (k - 512)])
                      : W[(long)wr * 512 + k];
        }
    };
    auto stB = [&](const float* p) {
#pragma unroll
        for (int z = 0; z < NB; z++) {
            int i = tid + z * 256;
            Bs[i & 7][i >> 3] = p[z];
        }
    };

    ull acc[RM][RJ][2];
#pragma unroll
    for (int im = 0; im < RM; im++)
#pragma unroll
        for (int ij = 0; ij < RJ; ij++) { acc[im][ij][0] = 0ull; acc[im][ij][1] = 0ull; }

    float pa[NA], pb[NB];
    ldA(0, pa); ldB(0, pb); stA(pa); stB(pb);
    __syncthreads();

    const int nk = K / 8;
    for (int kt = 0; kt < nk; kt++) {
        const bool more = (kt + 1) < nk;
        if (more) { ldA((kt + 1) * 8, pa); ldB((kt + 1) * 8, pb); }
#pragma unroll
        for (int kk = 0; kk < 8; kk++) {
            ull ad[RM];
#pragma unroll
            for (int im = 0; im < RM; im++) {
                float a = As[kk][ty * RM + im];
                ad[im] = pk2(a, a);
            }
#pragma unroll
            for (int ij = 0; ij < RJ; ij++) {
                const float4 b = *(const float4*)&Bs[kk][(tx * RJ + ij) * 4];
                ull b01 = pk2(b.x, b.y);
                ull b23 = pk2(b.z, b.w);
#pragma unroll
                for (int im = 0; im < RM; im++) {
                    FMA2(acc[im][ij][0], ad[im], b01);
                    FMA2(acc[im][ij][1], ad[im], b23);
                }
            }
        }
        __syncthreads();
        if (more) { stA(pa); stB(pb); }
        __syncthreads();
    }

    // epilogue: LSTM pointwise (+ optional ragged-mask commit)
#pragma unroll
    for (int im = 0; im < RM; im++) {
#pragma unroll
        for (int ij = 0; ij < RJ; ij++) {
            int m = m0 + ty * RM + im;
            int j = j0 + tx * RJ + ij;
            int idx = m * 512 + j;
            float vi, vf, vg, vo;
            upk2(acc[im][ij][0], vi, vf);
            upk2(acc[im][ij][1], vg, vo);
            if (HX) {
                const float* xr = xpre + (long)m * xstride;
                vi += xr[j]; vf += xr[512 + j]; vg += xr[1024 + j]; vo += xr[1536 + j];
            }
            if (HB) {
                vi += bias[j]; vf += bias[512 + j]; vg += bias[1024 + j]; vo += bias[1536 + j];
            }
            float c = sigf(vf) * c_in[idx] + sigf(vi) * tanhf(vg);
            float h = sigf(vo) * tanhf(c);
            if (!MK) {
                c_out[idx] = c;
                h_out[idx] = h;
            } else {
                bool upd = t < qlen[m / 5];
                h_out[idx] = upd ? h : A2[idx];       // A2 = old h2
                c_out[idx] = upd ? c : c_in[idx];     // c_in = old c2
                h1_o[idx]  = upd ? A[idx] : h1_in[idx];   // A = nh1
                c1_o[idx]  = upd ? nc1[idx] : c1_in[idx];
            }
        }
    }
}

// broadcast video-final states [64,512] -> text-init [320,512]
__global__ void bc_init(const float* __restrict__ sh1, const float* __restrict__ sc1,
                        const float* __restrict__ sh2, const float* __restrict__ sc2,
                        float* __restrict__ dh1, float* __restrict__ dc1,
                        float* __restrict__ dh2, float* __restrict__ dc2)
{
    int idx = blockIdx.x * blockDim.x + threadIdx.x;
    if (idx >= 320 * 512) return;
    int q = idx >> 9, j = idx & 511;
    int s = (q / 5) * 512 + j;
    dh1[idx] = sh1[s]; dc1[idx] = sc1[s];
    dh2[idx] = sh2[s]; dc2[idx] = sc2[s];
}

// outputs[m] = fe[m,:] . dec2_w + dec2_b   (one warp per m)
__global__ void dec2_k(const float* __restrict__ fe, const float* __restrict__ w,
                       const float* __restrict__ b, float* __restrict__ out)
{
    int warp = (blockIdx.x * blockDim.x + threadIdx.x) >> 5;
    int lane = threadIdx.x & 31;
    if (warp >= 320) return;
    float s = 0.f;
    for (int k = lane; k < 1024; k += 32) s += fe[(long)warp * 1024 + k] * w[k];
#pragma unroll
    for (int o = 16; o; o >>= 1) s += __shfl_xor_sync(0xFFFFFFFFu, s, o);
    if (lane == 0) out[warp] = s + b[0];
}

__global__ void argmax_k(const float* __restrict__ outv, float* __restrict__ pred)
{
    int b = threadIdx.x;
    if (b < 64) {
        float best = outv[b * 5]; int bi = 0;
#pragma unroll
        for (int n = 1; n < 5; n++) {
            float v = outv[b * 5 + n];
            if (v > best) { best = v; bi = n; }
        }
        pred[b] = (float)bi;
    }
}

// ---------------- host orchestration ----------------
extern "C" void kernel_launch(void* const* d_in, const int* in_sizes, int n_in,
                              void* d_out, int out_size)
{
    const float* vf      = (const float*)d_in[0];
    const int*   ques    = (const int*)  d_in[1];
    const int*   qlen    = (const int*)  d_in[2];
    const float* embed   = (const float*)d_in[3];
    const float* Wih_t1  = (const float*)d_in[4];
    const float* Whh_t1  = (const float*)d_in[5];
    const float* b_t1    = (const float*)d_in[6];
    const float* Wih_t2  = (const float*)d_in[7];
    const float* Whh_t2  = (const float*)d_in[8];
    const float* b_t2    = (const float*)d_in[9];
    const float* Wih_v1  = (const float*)d_in[10];
    const float* Whh_v1  = (const float*)d_in[11];
    const float* b_v1    = (const float*)d_in[12];
    const float* Wih_v2  = (const float*)d_in[13];
    const float* Whh_v2  = (const float*)d_in[14];
    const float* b_v2    = (const float*)d_in[15];
    const float* dec1_w  = (const float*)d_in[16];
    const float* dec1_b  = (const float*)d_in[17];
    const float* dec2_w  = (const float*)d_in[18];
    const float* dec2_b  = (const float*)d_in[19];
    float* out = (float*)d_out;

    float *Xv1, *Xt1, *h1, *c1, *h2, *c2, *nh1, *nc1, *fe;
    cudaGetSymbolAddress((void**)&Xv1, g_Xv1);
    cudaGetSymbolAddress((void**)&Xt1, g_Xt1);
    cudaGetSymbolAddress((void**)&h1,  g_h1);
    cudaGetSymbolAddress((void**)&c1,  g_c1);
    cudaGetSymbolAddress((void**)&h2,  g_h2);
    cudaGetSymbolAddress((void**)&c2,  g_c2);
    cudaGetSymbolAddress((void**)&nh1, g_nh1);
    cudaGetSymbolAddress((void**)&nc1, g_nc1);
    cudaGetSymbolAddress((void**)&fe,  g_fe);

    // zero video initial states (ping 0, 64 rows used)
    cudaMemsetAsync(h1, 0, 64 * 512 * sizeof(float));
    cudaMemsetAsync(c1, 0, 64 * 512 * sizeof(float));
    cudaMemsetAsync(h2, 0, 64 * 512 * sizeof(float));
    cudaMemsetAsync(c2, 0, 64 * 512 * sizeof(float));

    // Xv1 = vf @ Wih_v1^T + b_v1  : [1280, 2048], rows in natural (b*20+f) order
    sgemm2<0><<<dim3(16, 10), 256>>>(vf, nullptr, Wih_v1, b_v1, Xv1, 2048,
                                     1280, 8192, 8192, 1280, nullptr, nullptr);
    // Xt1 = emb @ Wih_t1^T + b_t1 : [6400, 2048], rows (l*320+q), K=300
    sgemm2<2><<<dim3(16, 50), 256>>>(nullptr, nullptr, Wih_t1, b_t1, Xt1, 2048,
                                     6400, 300, 300, 6400, ques, embed);

    // ---- video recurrence (M=64): TM=32, TJ=8 -> grid (64,2)=128 blocks ----
    int p = 0;
    for (int t = 0; t < 20; t++) {
        int q = p ^ 1;
        // cell1: gates = Xv1[row m*20+t] + h1 @ Whh_v1^T
        cell_k<32, 8, 1, 1, 0, 1, 0, 0><<<dim3(64, 2), 256>>>(
            h1 + p * SS, nullptr, Whh_v1, nullptr, nullptr,
            Xv1 + (long)t * 2048, 20 * 2048,
            c1 + p * SS, h1 + q * SS, c1 + q * SS,
            nullptr, nullptr, nullptr, nullptr, nullptr, nullptr, 0);
        // cell2: gates = [h1new | h2] @ [Wih_v2 | Whh_v2]^T + b_v2
        cell_k<32, 8, 1, 1, 1, 0, 1, 0><<<dim3(64, 2), 256>>>(
            h1 + q * SS, h2 + p * SS, Wih_v2, Whh_v2, b_v2,
            nullptr, 0,
            c2 + p * SS, h2 + q * SS, c2 + q * SS,
            nullptr, nullptr, nullptr, nullptr, nullptr, nullptr, 0);
        p = q;
    }

    // broadcast video-final states into text-init (other ping)
    int tp = p ^ 1;
    bc_init<<<640, 256>>>(h1 + p * SS, c1 + p * SS, h2 + p * SS, c2 + p * SS,
                          h1 + tp * SS, c1 + tp * SS, h2 + tp * SS, c2 + tp * SS);
    p = tp;

    // ---- text recurrence (M=320, masked): TM=32, TJ=32 -> grid (16,10)=160 ----
    for (int t = 0; t < 20; t++) {
        int q = p ^ 1;
        // cell1 candidate: gates = Xt1[t] + h1 @ Whh_t1^T  -> nh1, nc1
        cell_k<16, 16, 2, 2, 0, 1, 0, 0><<<dim3(16, 10), 256>>>(
            h1 + p * SS, nullptr, Whh_t1, nullptr, nullptr,
            Xt1 + (long)t * 320 * 2048, 2048,
            c1 + p * SS, nh1, nc1,
            nullptr, nullptr, nullptr, nullptr, nullptr, nullptr, 0);
        // cell2 + masked commit of all 4 states
        cell_k<16, 16, 2, 2, 1, 0, 1, 1><<<dim3(16, 10), 256>>>(
            nh1, h2 + p * SS, Wih_t2, Whh_t2, b_t2,
            nullptr, 0,
            c2 + p * SS, h2 + q * SS, c2 + q * SS,
            nc1, h1 + p * SS, c1 + p * SS, h1 + q * SS, c1 + q * SS,
            qlen, t);
        p = q;
    }

    // ---- decoder ----
    // fe = [h1, h2] @ dec1_w^T + dec1_b : [320, 1024], K=1024
    sgemm2<3><<<dim3(8, 3), 256>>>(h1 + p * SS, h2 + p * SS, dec1_w, dec1_b,
                                   fe, 1024, 320, 1024, 512, 320, nullptr, nullptr);
    dec2_k<<<10, 1024>>>(fe, dec2_w, dec2_b, out);
    if (out_size >= 384)
        argmax_k<<<1, 64>>>(out, out + 320);
}

// round 3
// speedup vs baseline: 1.7793x; 1.7253x over previous
#include <cuda_runtime.h>
#include <cuda_bf16.h>

typedef unsigned long long ull;

#define SS   (320*512)      // state buffer (rows*H)

// -------- device scratch (no allocation allowed) --------
__device__ float g_Xv1[1280L*2048];     // [B*F, 4H] rows (b*20+f): vf@Wih_v1^T + b_v1
__device__ float g_Xt1[6400L*2048];     // [L*BN, 4H]: emb@Wih_t1^T + b_t1
__device__ float g_h1[2*SS];
__device__ float g_c1[2*SS];
__device__ float g_h2[2*SS];
__device__ float g_c2[2*SS];
__device__ float g_nh1[SS];
__device__ float g_nc1[SS];
__device__ float g_fe[320*1024];

// ---- packed f32x2 helpers ----
__device__ __forceinline__ ull pk2(float lo, float hi) {
    ull r;
    asm("mov.b64 %0, {%1, %2};" : "=l"(r) : "f"(lo), "f"(hi));
    return r;
}
__device__ __forceinline__ void upk2(ull v, float& lo, float& hi) {
    asm("mov.b64 {%0, %1}, %2;" : "=f"(lo), "=f"(hi) : "l"(v));
}
#define FMA2(acc, a, b) asm("fma.rn.f32x2 %0, %1, %2, %3;" : "=l"(acc) : "l"(a), "l"(b), "l"(acc))

__device__ __forceinline__ float sigf(float x) { return 1.f / (1.f + expf(-x)); }

// =====================================================================
// sgemm3: 128(M) x 64(N) x K fp32 GEMM, BK=16, double-buffered smem,
// k-major smem layout (transposed STS), f32x2 inner.
// AM: 0 = direct A rows, 2 = embedding gather (row l*320+q -> token)
// out[m, n0+n] = sum_k A(m,k)*W[n,k] (+bias[n])
// =====================================================================
template<int AM>
__global__ __launch_bounds__(256)
void sgemm3(const float* __restrict__ A, const float* __restrict__ W,
            const float* __restrict__ bias, float* __restrict__ out,
            int Kfull, int lda,
            const int* __restrict__ ques, const float* __restrict__ emb)
{
    constexpr int BK = 16, ASTR = 132, BSTR = 68;
    __shared__ float As[2][BK * ASTR];
    __shared__ float Bs[2][BK * BSTR];

    const int tid = threadIdx.x;
    const int tx  = tid & 15;
    const int ty  = tid >> 4;
    const int m0  = blockIdx.y * 128;
    const int n0  = blockIdx.x * 64;

    float4 pa[2], pb;

    auto ldg = [&](int kb) {
#pragma unroll
        for (int z = 0; z < 2; z++) {
            int c = tid + z * 256, row = c >> 2, kq = (c & 3) * 4;
            int m = m0 + row, k = kb + kq;
            if (AM == 0) {
                pa[z] = *(const float4*)&A[(long)m * lda + k];
            } else {
                int qq = m % 320, l = m / 320;
                long tb = (long)ques[qq * 20 + l] * 300;
                float v[4];
#pragma unroll
                for (int i = 0; i < 4; i++) {
                    int kk = k + i;
                    v[i] = (kk < Kfull) ? emb[tb + kk] : 0.f;
                }
                pa[z] = make_float4(v[0], v[1], v[2], v[3]);
            }
        }
        {
            int c = tid, r = c >> 2, kq = (c & 3) * 4;
            int n = n0 + r, k = kb + kq;
            if (AM == 0) {
                pb = *(const float4*)&W[(long)n * lda + k];
            } else {
                float v[4];
#pragma unroll
                for (int i = 0; i < 4; i++)
                    v[i] = (k + i < Kfull) ? W[(long)n * Kfull + k + i] : 0.f;
                pb = make_float4(v[0], v[1], v[2], v[3]);
            }
        }
    };
    auto sts = [&](int s) {
#pragma unroll
        for (int z = 0; z < 2; z++) {
            int c = tid + z * 256, row = c >> 2, kq = (c & 3) * 4;
            As[s][(kq + 0) * ASTR + row] = pa[z].x;
            As[s][(kq + 1) * ASTR + row] = pa[z].y;
            As[s][(kq + 2) * ASTR + row] = pa[z].z;
            As[s][(kq + 3) * ASTR + row] = pa[z].w;
        }
        {
            int c = tid, r = c >> 2, kq = (c & 3) * 4;
            Bs[s][(kq + 0) * BSTR + r] = pb.x;
            Bs[s][(kq + 1) * BSTR + r] = pb.y;
            Bs[s][(kq + 2) * BSTR + r] = pb.z;
            Bs[s][(kq + 3) * BSTR + r] = pb.w;
        }
    };

    ull acc[8][2];
#pragma unroll
    for (int i = 0; i < 8; i++) { acc[i][0] = 0ull; acc[i][1] = 0ull; }

    ldg(0); sts(0); __syncthreads();
    const int nkt = (Kfull + BK - 1) / BK;
    for (int kt = 0; kt < nkt; kt++) {
        const int s = kt & 1;
        if (kt + 1 < nkt) ldg((kt + 1) * BK);
#pragma unroll
        for (int kk = 0; kk < BK; kk++) {
            const float4 a0 = *(const float4*)&As[s][kk * ASTR + ty * 8];
            const float4 a1 = *(const float4*)&As[s][kk * ASTR + ty * 8 + 4];
            const ulonglong2 bv = *(const ulonglong2*)&Bs[s][kk * BSTR + tx * 4];
            float av[8] = { a0.x, a0.y, a0.z, a0.w, a1.x, a1.y, a1.z, a1.w };
#pragma unroll
            for (int im = 0; im < 8; im++) {
                ull ad = pk2(av[im], av[im]);
                FMA2(acc[im][0], ad, bv.x);
                FMA2(acc[im][1], ad, bv.y);
            }
        }
        if (kt + 1 < nkt) sts(s ^ 1);
        __syncthreads();
    }

#pragma unroll
    for (int im = 0; im < 8; im++) {
        int m = m0 + ty * 8 + im;
        long ro = (long)m * 2048 + n0 + tx * 4;
        float v0, v1, v2, v3;
        upk2(acc[im][0], v0, v1);
        upk2(acc[im][1], v2, v3);
        if (bias) {
            v0 += bias[n0 + tx * 4 + 0]; v1 += bias[n0 + tx * 4 + 1];
            v2 += bias[n0 + tx * 4 + 2]; v3 += bias[n0 + tx * 4 + 3];
        }
        out[ro + 0] = v0; out[ro + 1] = v1; out[ro + 2] = v2; out[ro + 3] = v3;
    }
}

// =====================================================================
// cell_k3: fused LSTM cell, BK=16, double-buffered, k-major smem.
// Block computes TM rows x TJ h-cols (x4 gates); epilogue = pointwise.
// B smem rows ordered (jl, gate): row = jl*4 + g  -> ulonglong2 reads
// give (i,f) and (g,o) pairs directly.
// =====================================================================
template<int TY, int TX, int RM, int RJ, int CC, int HX, int HB, int MK>
__global__ __launch_bounds__(256)
void cell_k3(const float* __restrict__ A, const float* __restrict__ A2,
             const float* __restrict__ W, const float* __restrict__ W2,
             const float* __restrict__ bias,
             const float* __restrict__ xpre, int xstride,
             const float* __restrict__ c_in,
             float* __restrict__ h_out, float* __restrict__ c_out,
             const float* __restrict__ nc1p,
             const float* __restrict__ h1_in, const float* __restrict__ c1_in,
             float* __restrict__ h1_o, float* __restrict__ c1_o,
             const int* __restrict__ qlen, int t)
{
    constexpr int TM = TY * RM;
    constexpr int TJ = TX * RJ;
    constexpr int GC = 4 * TJ;
    constexpr int K  = CC ? 1024 : 512;
    constexpr int BK = 16;
    constexpr int ASTR = TM + 4;
    constexpr int BSTR = GC + 4;
    constexpr int NCA = (TM * 4) / 256;          // chunks of A per thread (=1)
    constexpr int NCB = (GC * 4 + 255) / 256;    // chunks of B per thread (guarded)

    __shared__ float As[2][BK * ASTR];
    __shared__ float Bs[2][BK * BSTR];

    const int tid = threadIdx.x;
    const int tx  = tid % TX;
    const int ty  = tid / TX;
    const int m0  = blockIdx.y * TM;
    const int j0  = blockIdx.x * TJ;

    float4 pa[NCA], pb[NCB];

    auto ldg = [&](int kb) {
#pragma unroll
        for (int z = 0; z < NCA; z++) {
            int c = tid + z * 256, row = c >> 2, kq = (c & 3) * 4;
            int m = m0 + row, k = kb + kq;
            pa[z] = CC ? ((k < 512) ? *(const float4*)&A[(long)m * 512 + k]
                                    : *(const float4*)&A2[(long)m * 512 + (k - 512)])
                       : *(const float4*)&A[(long)m * 512 + k];
        }
#pragma unroll
        for (int z = 0; z < NCB; z++) {
            int c = tid + z * 256;
            if (c < GC * 4) {
                int r = c >> 2, kq = (c & 3) * 4;
                int jl = r >> 2, g = r & 3;
                int wr = g * 512 + j0 + jl, k = kb + kq;
                pb[z] = CC ? ((k < 512) ? *(const float4*)&W[(long)wr * 512 + k]
                                        : *(const float4*)&W2[(long)wr * 512 + (k - 512)])
                           : *(const float4*)&W[(long)wr * 512 + k];
            }
        }
    };
    auto sts = [&](int s) {
#pragma unroll
        for (int z = 0; z < NCA; z++) {
            int c = tid + z * 256, row = c >> 2, kq = (c & 3) * 4;
            As[s][(kq + 0) * ASTR + row] = pa[z].x;
            As[s][(kq + 1) * ASTR + row] = pa[z].y;
            As[s][(kq + 2) * ASTR + row] = pa[z].z;
            As[s][(kq + 3) * ASTR + row] = pa[z].w;
        }
#pragma unroll
        for (int z = 0; z < NCB; z++) {
            int c = tid + z * 256;
            if (c < GC * 4) {
                int r = c >> 2, kq = (c & 3) * 4;
                Bs[s][(kq + 0) * BSTR + r] = pb[z].x;
                Bs[s][(kq + 1) * BSTR + r] = pb[z].y;
                Bs[s][(kq + 2) * BSTR + r] = pb[z].z;
                Bs[s][(kq + 3) * BSTR + r] = pb[z].w;
            }
        }
    };

    ull acc[RM][RJ][2];
#pragma unroll
    for (int im = 0; im < RM; im++)
#pragma unroll
        for (int ij = 0; ij < RJ; ij++) { acc[im][ij][0] = 0ull; acc[im][ij][1] = 0ull; }

    ldg(0); sts(0); __syncthreads();
    constexpr int NKT = K / BK;
    for (int kt = 0; kt < NKT; kt++) {
        const int s = kt & 1;
        if (kt + 1 < NKT) ldg((kt + 1) * BK);
#pragma unroll
        for (int kk = 0; kk < BK; kk++) {
            ull ad[RM];
            if (RM == 4) {
                const float4 av = *(const float4*)&As[s][kk * ASTR + ty * RM];
                ad[0] = pk2(av.x, av.x); ad[1] = pk2(av.y, av.y);
                ad[2] = pk2(av.z, av.z); ad[3] = pk2(av.w, av.w);
            } else {
                const float2 av = *(const float2*)&As[s][kk * ASTR + ty * RM];
                ad[0] = pk2(av.x, av.x); ad[1] = pk2(av.y, av.y);
            }
#pragma unroll
            for (int ij = 0; ij < RJ; ij++) {
                const ulonglong2 bv =
                    *(const ulonglong2*)&Bs[s][kk * BSTR + (tx * RJ + ij) * 4];
#pragma unroll
                for (int im = 0; im < RM; im++) {
                    FMA2(acc[im][ij][0], ad[im], bv.x);
                    FMA2(acc[im][ij][1], ad[im], bv.y);
                }
            }
        }
        if (kt + 1 < NKT) sts(s ^ 1);
        __syncthreads();
    }

    // epilogue: LSTM pointwise (+ optional ragged-mask commit)
#pragma unroll
    for (int im = 0; im < RM; im++) {
#pragma unroll
        for (int ij = 0; ij < RJ; ij++) {
            int m = m0 + ty * RM + im;
            int j = j0 + tx * RJ + ij;
            int idx = m * 512 + j;
            float vi, vf, vg, vo;
            upk2(acc[im][ij][0], vi, vf);
            upk2(acc[im][ij][1], vg, vo);
            if (HX) {
                const float* xr = xpre + (long)m * xstride;
                vi += xr[j]; vf += xr[512 + j]; vg += xr[1024 + j]; vo += xr[1536 + j];
            }
            if (HB) {
                vi += bias[j]; vf += bias[512 + j]; vg += bias[1024 + j]; vo += bias[1536 + j];
            }
            float c = sigf(vf) * c_in[idx] + sigf(vi) * tanhf(vg);
            float h = sigf(vo) * tanhf(c);
            if (!MK) {
                c_out[idx] = c;
                h_out[idx] = h;
            } else {
                bool upd = t < qlen[m / 5];
                h_out[idx] = upd ? h : A2[idx];         // A2 = old h2
                c_out[idx] = upd ? c : c_in[idx];       // c_in = old c2
                h1_o[idx]  = upd ? A[idx] : h1_in[idx]; // A = nh1
                c1_o[idx]  = upd ? nc1p[idx] : c1_in[idx];
            }
        }
    }
}

// =====================================================================
// dec1 GEMM (small): concat [h1|h2] @ dec1_w^T + b  -- legacy engine
// =====================================================================
__global__ __launch_bounds__(256)
void dec1_k(const float* __restrict__ A, const float* __restrict__ A2,
            const float* __restrict__ W, const float* __restrict__ bias,
            float* __restrict__ out)
{
    __shared__ float As[8][128];
    __shared__ float Bs[8][128];
    const int tid = threadIdx.x;
    const int r   = tid >> 1;
    const int kq  = (tid & 1) * 4;
    const int m0  = blockIdx.y * 128;
    const int n0  = blockIdx.x * 128;
    const int tx  = tid & 15;
    const int ty  = tid >> 4;
    const int m   = m0 + r;
    const int n   = n0 + r;

    float acc[8][8];
#pragma unroll
    for (int i = 0; i < 8; i++)
#pragma unroll
        for (int j = 0; j < 8; j++) acc[i][j] = 0.f;

    for (int kt = 0; kt < 128; kt++) {
        const int kb = kt * 8;
#pragma unroll
        for (int i = 0; i < 4; i++) {
            int k = kb + kq + i;
            As[kq + i][r] = (m < 320) ? ((k < 512) ? A[(long)m * 512 + k]
                                                   : A2[(long)m * 512 + (k - 512)]) : 0.f;
            Bs[kq + i][r] = W[(long)n * 1024 + k];
        }
        __syncthreads();
#pragma unroll
        for (int kk = 0; kk < 8; kk++) {
            float a[8], b[8];
#pragma unroll
            for (int i = 0; i < 8; i++) a[i] = As[kk][ty * 8 + i];
#pragma unroll
            for (int j = 0; j < 8; j++) b[j] = Bs[kk][tx * 8 + j];
#pragma unroll
            for (int i = 0; i < 8; i++)
#pragma unroll
                for (int j = 0; j < 8; j++) acc[i][j] += a[i] * b[j];
        }
        __syncthreads();
    }
#pragma unroll
    for (int i = 0; i < 8; i++) {
        int mm = m0 + ty * 8 + i;
        if (mm < 320) {
            long ro = (long)mm * 1024 + n0 + tx * 8;
#pragma unroll
            for (int j = 0; j < 8; j++)
                out[ro + j] = acc[i][j] + bias[n0 + tx * 8 + j];
        }
    }
}

// broadcast video-final states [64,512] -> text-init [320,512]
__global__ void bc_init(const float* __restrict__ sh1, const float* __restrict__ sc1,
                        const float* __restrict__ sh2, const float* __restrict__ sc2,
                        float* __restrict__ dh1, float* __restrict__ dc1,
                        float* __restrict__ dh2, float* __restrict__ dc2)
{
    int idx = blockIdx.x * blockDim.x + threadIdx.x;
    if (idx >= 320 * 512) return;
    int q = idx >> 9, j = idx & 511;
    int s = (q / 5) * 512 + j;
    dh1[idx] = sh1[s]; dc1[idx] = sc1[s];
    dh2[idx] = sh2[s]; dc2[idx] = sc2[s];
}

// outputs[m] = fe[m,:] . dec2_w + dec2_b   (one warp per m)
__global__ void dec2_k(const float* __restrict__ fe, const float* __restrict__ w,
                       const float* __restrict__ b, float* __restrict__ out)
{
    int warp = (blockIdx.x * blockDim.x + threadIdx.x) >> 5;
    int lane = threadIdx.x & 31;
    if (warp >= 320) return;
    float s = 0.f;
    for (int k = lane; k < 1024; k += 32) s += fe[(long)warp * 1024 + k] * w[k];
#pragma unroll
    for (int o = 16; o; o >>= 1) s += __shfl_xor_sync(0xFFFFFFFFu, s, o);
    if (lane == 0) out[warp] = s + b[0];
}

__global__ void argmax_k(const float* __restrict__ outv, float* __restrict__ pred)
{
    int b = threadIdx.x;
    if (b < 64) {
        float best = outv[b * 5]; int bi = 0;
#pragma unroll
        for (int n = 1; n < 5; n++) {
            float v = outv[b * 5 + n];
            if (v > best) { best = v; bi = n; }
        }
        pred[b] = (float)bi;
    }
}

// ---------------- host orchestration ----------------
extern "C" void kernel_launch(void* const* d_in, const int* in_sizes, int n_in,
                              void* d_out, int out_size)
{
    const float* vf      = (const float*)d_in[0];
    const int*   ques    = (const int*)  d_in[1];
    const int*   qlen    = (const int*)  d_in[2];
    const float* embed   = (const float*)d_in[3];
    const float* Wih_t1  = (const float*)d_in[4];
    const float* Whh_t1  = (const float*)d_in[5];
    const float* b_t1    = (const float*)d_in[6];
    const float* Wih_t2  = (const float*)d_in[7];
    const float* Whh_t2  = (const float*)d_in[8];
    const float* b_t2    = (const float*)d_in[9];
    const float* Wih_v1  = (const float*)d_in[10];
    const float* Whh_v1  = (const float*)d_in[11];
    const float* b_v1    = (const float*)d_in[12];
    const float* Wih_v2  = (const float*)d_in[13];
    const float* Whh_v2  = (const float*)d_in[14];
    const float* b_v2    = (const float*)d_in[15];
    const float* dec1_w  = (const float*)d_in[16];
    const float* dec1_b  = (const float*)d_in[17];
    const float* dec2_w  = (const float*)d_in[18];
    const float* dec2_b  = (const float*)d_in[19];
    float* out = (float*)d_out;

    float *Xv1, *Xt1, *h1, *c1, *h2, *c2, *nh1, *nc1, *fe;
    cudaGetSymbolAddress((void**)&Xv1, g_Xv1);
    cudaGetSymbolAddress((void**)&Xt1, g_Xt1);
    cudaGetSymbolAddress((void**)&h1,  g_h1);
    cudaGetSymbolAddress((void**)&c1,  g_c1);
    cudaGetSymbolAddress((void**)&h2,  g_h2);
    cudaGetSymbolAddress((void**)&c2,  g_c2);
    cudaGetSymbolAddress((void**)&nh1, g_nh1);
    cudaGetSymbolAddress((void**)&nc1, g_nc1);
    cudaGetSymbolAddress((void**)&fe,  g_fe);

    // zero video initial states (ping 0, 64 rows used)
    cudaMemsetAsync(h1, 0, 64 * 512 * sizeof(float));
    cudaMemsetAsync(c1, 0, 64 * 512 * sizeof(float));
    cudaMemsetAsync(h2, 0, 64 * 512 * sizeof(float));
    cudaMemsetAsync(c2, 0, 64 * 512 * sizeof(float));

    // Xv1 = vf @ Wih_v1^T + b_v1 : [1280, 2048], K=8192
    sgemm3<0><<<dim3(32, 10), 256>>>(vf, Wih_v1, b_v1, Xv1, 8192, 8192,
                                     nullptr, nullptr);
    // Xt1 = emb @ Wih_t1^T + b_t1 : [6400, 2048], K=300 (gather)
    sgemm3<2><<<dim3(32, 50), 256>>>(nullptr, Wih_t1, b_t1, Xt1, 300, 300,
                                     ques, embed);

    // ---- video recurrence (M=64): TM=64, TJ=8 -> grid (64,1) ----
    int p = 0;
    for (int t = 0; t < 20; t++) {
        int q = p ^ 1;
        // cell1: gates = Xv1[row m*20+t] + h1 @ Whh_v1^T
        cell_k3<32, 8, 2, 1, 0, 1, 0, 0><<<dim3(64, 1), 256>>>(
            h1 + p * SS, nullptr, Whh_v1, nullptr, nullptr,
            Xv1 + (long)t * 2048, 20 * 2048,
            c1 + p * SS, h1 + q * SS, c1 + q * SS,
            nullptr, nullptr, nullptr, nullptr, nullptr, nullptr, 0);
        // cell2: gates = [h1new | h2] @ [Wih_v2 | Whh_v2]^T + b_v2
        cell_k3<32, 8, 2, 1, 1, 0, 1, 0><<<dim3(64, 1), 256>>>(
            h1 + q * SS, h2 + p * SS, Wih_v2, Whh_v2, b_v2,
            nullptr, 0,
            c2 + p * SS, h2 + q * SS, c2 + q * SS,
            nullptr, nullptr, nullptr, nullptr, nullptr, nullptr, 0);
        p = q;
    }

    // broadcast video-final states into text-init (other ping)
    int tp = p ^ 1;
    bc_init<<<640, 256>>>(h1 + p * SS, c1 + p * SS, h2 + p * SS, c2 + p * SS,
                          h1 + tp * SS, c1 + tp * SS, h2 + tp * SS, c2 + tp * SS);
    p = tp;

    // ---- text recurrence (M=320, masked): TM=64, TJ=32 -> grid (16,5) ----
    for (int t = 0; t < 20; t++) {
        int q = p ^ 1;
        // cell1 candidate: gates = Xt1[t] + h1 @ Whh_t1^T -> nh1, nc1
        cell_k3<16, 16, 4, 2, 0, 1, 0, 0><<<dim3(16, 5), 256>>>(
            h1 + p * SS, nullptr, Whh_t1, nullptr, nullptr,
            Xt1 + (long)t * 320 * 2048, 2048,
            c1 + p * SS, nh1, nc1,
            nullptr, nullptr, nullptr, nullptr, nullptr, nullptr, 0);
        // cell2 + masked commit of all 4 states
        cell_k3<16, 16, 4, 2, 1, 0, 1, 1><<<dim3(16, 5), 256>>>(
            nh1, h2 + p * SS, Wih_t2, Whh_t2, b_t2,
            nullptr, 0,
            c2 + p * SS, h2 + q * SS, c2 + q * SS,
            nc1, h1 + p * SS, c1 + p * SS, h1 + q * SS, c1 + q * SS,
            qlen, t);
        p = q;
    }

    // ---- decoder ----
    dec1_k<<<dim3(8, 3), 256>>>(h1 + p * SS, h2 + p * SS, dec1_w, dec1_b, fe);
    dec2_k<<<10, 1024>>>(fe, dec2_w, dec2_b, out);
    if (out_size >= 384)
        argmax_k<<<1, 64>>>(out, out + 320);
}

// round 6
// speedup vs baseline: 2.0513x; 1.1529x over previous
#include <cuda_runtime.h>

typedef unsigned long long ull;

#define SS   (320*512)      // text state buffer (rows*H)

// -------- device scratch (no allocation allowed) --------
__device__ float g_Xv1[1280L*2048];     // [B*F, 4H] rows (b*20+f): vf@Wih_v1^T + b_v1
__device__ float g_Xt1[6400L*2048];     // [L*BN, 4H] rows (l*320+q): emb@Wih_t1^T + b_t1
__device__ float g_part[8L*64*2048];    // split-K partials (video cells)
__device__ float g_vh1[64*512];         // video states (in-place)
__device__ float g_vc1[64*512];
__device__ float g_vh2[64*512];
__device__ float g_vc2[64*512];
__device__ float g_h1[2*SS];            // text ping-pong
__device__ float g_c1[2*SS];
__device__ float g_h2[2*SS];
__device__ float g_c2[2*SS];
__device__ float g_nh1[SS];
__device__ float g_nc1[SS];
__device__ float g_fe[320*1024];

// ---- packed f32x2 helpers ----
__device__ __forceinline__ ull pk2(float lo, float hi) {
    ull r;
    asm("mov.b64 %0, {%1, %2};" : "=l"(r) : "f"(lo), "f"(hi));
    return r;
}
__device__ __forceinline__ void upk2(ull v, float& lo, float& hi) {
    asm("mov.b64 {%0, %1}, %2;" : "=f"(lo), "=f"(hi) : "l"(v));
}
#define FMA2(acc, a, b) asm("fma.rn.f32x2 %0, %1, %2, %3;" : "=l"(acc) : "l"(a), "l"(b), "l"(acc))

__device__ __forceinline__ float sigf(float x) { return 1.f / (1.f + expf(-x)); }

// =====================================================================
// vgemm: split-K video cell GEMM.  gates-partial[kz][m][n] =
//   sum_{k in chunk kz} Acat(m,k) * Wcat[n0+n, k]
// Block = 128 gate-cols x 64 rows x KS k-chunk. grid (16, K/KS).
// CC=1: concat A=[A|A2], W=[W|W2] at k=512.
// =====================================================================
template<int KS, int CC>
__global__ __launch_bounds__(256)
void vgemm(const float* __restrict__ A, const float* __restrict__ A2,
           const float* __restrict__ W, const float* __restrict__ W2,
           float* __restrict__ part)
{
    extern __shared__ float sm[];
    float* As = sm;              // 64 x KS, row-major
    float* Bs = sm + 64 * KS;    // KS x 128, k-major, XOR-swizzled

    const int tid = threadIdx.x;
    const int n0 = blockIdx.x * 128;
    const int kbase = blockIdx.y * KS;

    // fill A (row-major, coalesced loads)
#pragma unroll
    for (int z = 0; z < KS / 16; z++) {
        int c = tid + z * 256;
        int m = c / (KS / 4), k4 = c % (KS / 4);
        int gk = kbase + k4 * 4;
        float4 v;
        if (!CC || gk < 512) v = *(const float4*)&A[m * 512 + gk];
        else                 v = *(const float4*)&A2[m * 512 + gk - 512];
        *(float4*)&As[m * KS + k4 * 4] = v;
    }
    // fill B (k-major transpose with XOR swizzle: phys n' = n ^ ((k>>2 & 15)*2))
#pragma unroll
    for (int z = 0; z < KS / 8; z++) {
        int c = tid + z * 256;
        int n = c / (KS / 4), k4 = c % (KS / 4);
        int gk = kbase + k4 * 4;
        float4 v;
        if (!CC || gk < 512) v = *(const float4*)&W[(long)(n0 + n) * 512 + gk];
        else                 v = *(const float4*)&W2[(long)(n0 + n) * 512 + gk - 512];
        int nsw = n ^ ((k4 & 15) * 2);
        Bs[(k4 * 4 + 0) * 128 + nsw] = v.x;
        Bs[(k4 * 4 + 1) * 128 + nsw] = v.y;
        Bs[(k4 * 4 + 2) * 128 + nsw] = v.z;
        Bs[(k4 * 4 + 3) * 128 + nsw] = v.w;
    }
    __syncthreads();

    const int tx = tid & 15, ty = tid >> 4;
    ull acc[4][4];
#pragma unroll
    for (int rm = 0; rm < 4; rm++)
#pragma unroll
        for (int s = 0; s < 4; s++) acc[rm][s] = 0ull;

#pragma unroll 4
    for (int kk = 0; kk < KS; kk++) {
        const int swr = ((kk >> 2) & 15) * 2;
        ull b[4];
#pragma unroll
        for (int s = 0; s < 4; s++)
            b[s] = *(const ull*)&Bs[kk * 128 + ((tx * 2 + s * 32) ^ swr)];
#pragma unroll
        for (int rm = 0; rm < 4; rm++) {
            float a = As[(ty * 4 + rm) * KS + kk];
            ull ad = pk2(a, a);
            FMA2(acc[rm][0], ad, b[0]);
            FMA2(acc[rm][1], ad, b[1]);
            FMA2(acc[rm][2], ad, b[2]);
            FMA2(acc[rm][3], ad, b[3]);
        }
    }

    float* op = part + (long)blockIdx.y * (64 * 2048) + n0;
#pragma unroll
    for (int rm = 0; rm < 4; rm++) {
        int m = ty * 4 + rm;
#pragma unroll
        for (int s = 0; s < 4; s++) {
            float lo, hi;
            upk2(acc[rm][s], lo, hi);
            *(float2*)&op[(long)m * 2048 + tx * 2 + s * 32] = make_float2(lo, hi);
        }
    }
}

// video pointwise: sum 8 partials (+xpre or +bias), LSTM update in-place.
__global__ void vpw(const float* __restrict__ part,
                    const float* __restrict__ xpre, long xstride,
                    const float* __restrict__ bias,
                    float* __restrict__ h, float* __restrict__ c)
{
    int idx = blockIdx.x * 256 + threadIdx.x;   // 64*512 items, grid 128
    int m = idx >> 9, j = idx & 511;
    float g[4];
#pragma unroll
    for (int gi = 0; gi < 4; gi++) {
        int col = gi * 512 + j;
        float s = bias ? bias[col] : xpre[(long)m * xstride + col];
#pragma unroll
        for (int z = 0; z < 8; z++)
            s += part[(long)z * 64 * 2048 + (long)m * 2048 + col];
        g[gi] = s;
    }
    float cc = sigf(g[1]) * c[idx] + sigf(g[0]) * tanhf(g[2]);
    c[idx] = cc;
    h[idx] = sigf(g[3]) * tanhf(cc);
}

// =====================================================================
// cell_k3 (R3, proven): fused text LSTM cell, BK=16, double-buffered.
// =====================================================================
template<int TY, int TX, int RM, int RJ, int CC, int HX, int HB, int MK>
__global__ __launch_bounds__(256)
void cell_k3(const float* __restrict__ A, const float* __restrict__ A2,
             const float* __restrict__ W, const float* __restrict__ W2,
             const float* __restrict__ bias,
             const float* __restrict__ xpre, int xstride,
             const float* __restrict__ c_in,
             float* __restrict__ h_out, float* __restrict__ c_out,
             const float* __restrict__ nc1p,
             const float* __restrict__ h1_in, const float* __restrict__ c1_in,
             float* __restrict__ h1_o, float* __restrict__ c1_o,
             const int* __restrict__ qlen, int t)
{
    constexpr int TM = TY * RM;
    constexpr int TJ = TX * RJ;
    constexpr int GC = 4 * TJ;
    constexpr int K  = CC ? 1024 : 512;
    constexpr int BK = 16;
    constexpr int ASTR = TM + 4;
    constexpr int BSTR = GC + 4;
    constexpr int NCA = (TM * 4) / 256;
    constexpr int NCB = (GC * 4 + 255) / 256;

    __shared__ float As[2][BK * ASTR];
    __shared__ float Bs[2][BK * BSTR];

    const int tid = threadIdx.x;
    const int tx  = tid % TX;
    const int ty  = tid / TX;
    const int m0  = blockIdx.y * TM;
    const int j0  = blockIdx.x * TJ;

    float4 pa[NCA], pb[NCB];

    auto ldg = [&](int kb) {
#pragma unroll
        for (int z = 0; z < NCA; z++) {
            int i = tid + z * 256;
            int row = i >> 2, kq = (i & 3) * 4;
            int m = m0 + row, k = kb + kq;
            pa[z] = CC ? ((k < 512) ? *(const float4*)&A[(long)m * 512 + k]
                                    : *(const float4*)&A2[(long)m * 512 + (k - 512)])
                       : *(const float4*)&A[(long)m * 512 + k];
        }
#pragma unroll
        for (int z = 0; z < NCB; z++) {
            int i = tid + z * 256;
            if (i < GC * 4) {
                int r = i >> 2, kq = (i & 3) * 4;
                int jl = r >> 2, g = r & 3;
                int wr = g * 512 + j0 + jl, k = kb + kq;
                pb[z] = CC ? ((k < 512) ? *(const float4*)&W[(long)wr * 512 + k]
                                        : *(const float4*)&W2[(long)wr * 512 + (k - 512)])
                           : *(const float4*)&W[(long)wr * 512 + k];
            }
        }
    };
    auto sts = [&](int s) {
#pragma unroll
        for (int z = 0; z < NCA; z++) {
            int i = tid + z * 256;
            int row = i >> 2, kq = (i & 3) * 4;
            As[s][(kq + 0) * ASTR + row] = pa[z].x;
            As[s][(kq + 1) * ASTR + row] = pa[z].y;
            As[s][(kq + 2) * ASTR + row] = pa[z].z;
            As[s][(kq + 3) * ASTR + row] = pa[z].w;
        }
#pragma unroll
        for (int z = 0; z < NCB; z++) {
            int i = tid + z * 256;
            if (i < GC * 4) {
                int r = i >> 2, kq = (i & 3) * 4;
                Bs[s][(kq + 0) * BSTR + r] = pb[z].x;
                Bs[s][(kq + 1) * BSTR + r] = pb[z].y;
                Bs[s][(kq + 2) * BSTR + r] = pb[z].z;
                Bs[s][(kq + 3) * BSTR + r] = pb[z].w;
            }
        }
    };

    ull acc[RM][RJ][2];
#pragma unroll
    for (int im = 0; im < RM; im++)
#pragma unroll
        for (int ij = 0; ij < RJ; ij++) { acc[im][ij][0] = 0ull; acc[im][ij][1] = 0ull; }

    ldg(0); sts(0); __syncthreads();
    constexpr int NKT = K / BK;
    for (int kt = 0; kt < NKT; kt++) {
        const int s = kt & 1;
        if (kt + 1 < NKT) ldg((kt + 1) * BK);
#pragma unroll
        for (int kk = 0; kk < BK; kk++) {
            ull ad[RM];
            if (RM == 4) {
                const float4 av = *(const float4*)&As[s][kk * ASTR + ty * RM];
                ad[0] = pk2(av.x, av.x); ad[1] = pk2(av.y, av.y);
                ad[2] = pk2(av.z, av.z); ad[3] = pk2(av.w, av.w);
            } else {
                const float2 av = *(const float2*)&As[s][kk * ASTR + ty * RM];
                ad[0] = pk2(av.x, av.x); ad[1] = pk2(av.y, av.y);
            }
#pragma unroll
            for (int ij = 0; ij < RJ; ij++) {
                const ulonglong2 bv =
                    *(const ulonglong2*)&Bs[s][kk * BSTR + (tx * RJ + ij) * 4];
#pragma unroll
                for (int im = 0; im < RM; im++) {
                    FMA2(acc[im][ij][0], ad[im], bv.x);
                    FMA2(acc[im][ij][1], ad[im], bv.y);
                }
            }
        }
        if (kt + 1 < NKT) sts(s ^ 1);
        __syncthreads();
    }

#pragma unroll
    for (int im = 0; im < RM; im++) {
#pragma unroll
        for (int ij = 0; ij < RJ; ij++) {
            int m = m0 + ty * RM + im;
            int j = j0 + tx * RJ + ij;
            int idx = m * 512 + j;
            float vi, vf, vg, vo;
            upk2(acc[im][ij][0], vi, vf);
            upk2(acc[im][ij][1], vg, vo);
            if (HX) {
                const float* xr = xpre + (long)m * xstride;
                vi += xr[j]; vf += xr[512 + j]; vg += xr[1024 + j]; vo += xr[1536 + j];
            }
            if (HB) {
                vi += bias[j]; vf += bias[512 + j]; vg += bias[1024 + j]; vo += bias[1536 + j];
            }
            float c = sigf(vf) * c_in[idx] + sigf(vi) * tanhf(vg);
            float h = sigf(vo) * tanhf(c);
            if (!MK) {
                c_out[idx] = c;
                h_out[idx] = h;
            } else {
                bool upd = t < qlen[m / 5];
                h_out[idx] = upd ? h : A2[idx];         // A2 = old h2
                c_out[idx] = upd ? c : c_in[idx];       // c_in = old c2
                h1_o[idx]  = upd ? A[idx] : h1_in[idx]; // A = nh1
                c1_o[idx]  = upd ? nc1p[idx] : c1_in[idx];
            }
        }
    }
}

// =====================================================================
// sgemm3 (R3, proven): 128x64xK GEMM, BK=16 double-buffered, f32x2.
// AM: 0 = direct, 2 = embedding gather.
// =====================================================================
template<int AM>
__global__ __launch_bounds__(256)
void sgemm3(const float* __restrict__ A, const float* __restrict__ W,
            const float* __restrict__ bias, float* __restrict__ out,
            int Kfull, int lda,
            const int* __restrict__ ques, const float* __restrict__ emb)
{
    constexpr int BK = 16, ASTR = 132, BSTR = 68;
    __shared__ float As[2][BK * ASTR];
    __shared__ float Bs[2][BK * BSTR];

    const int tid = threadIdx.x;
    const int tx  = tid & 15;
    const int ty  = tid >> 4;
    const int m0  = blockIdx.y * 128;
    const int n0  = blockIdx.x * 64;

    float4 pa[2], pb;

    auto ldg = [&](int kb) {
#pragma unroll
        for (int z = 0; z < 2; z++) {
            int c = tid + z * 256, row = c >> 2, kq = (c & 3) * 4;
            int m = m0 + row, k = kb + kq;
            if (AM == 0) {
                pa[z] = *(const float4*)&A[(long)m * lda + k];
            } else {
                int qq = m % 320, l = m / 320;
                long tb = (long)ques[qq * 20 + l] * 300;
                float v[4];
#pragma unroll
                for (int i = 0; i < 4; i++) {
                    int kk = k + i;
                    v[i] = (kk < Kfull) ? emb[tb + kk] : 0.f;
                }
                pa[z] = make_float4(v[0], v[1], v[2], v[3]);
            }
        }
        {
            int c = tid, r = c >> 2, kq = (c & 3) * 4;
            int n = n0 + r, k = kb + kq;
            if (AM == 0) {
                pb = *(const float4*)&W[(long)n * lda + k];
            } else {
                float v[4];
#pragma unroll
                for (int i = 0; i < 4; i++)
                    v[i] = (k + i < Kfull) ? W[(long)n * Kfull + k + i] : 0.f;
                pb = make_float4(v[0], v[1], v[2], v[3]);
            }
        }
    };
    auto sts = [&](int s) {
#pragma unroll
        for (int z = 0; z < 2; z++) {
            int c = tid + z * 256, row = c >> 2, kq = (c & 3) * 4;
            As[s][(kq + 0) * ASTR + row] = pa[z].x;
            As[s][(kq + 1) * ASTR + row] = pa[z].y;
            As[s][(kq + 2) * ASTR + row] = pa[z].z;
            As[s][(kq + 3) * ASTR + row] = pa[z].w;
        }
        {
            int c = tid, r = c >> 2, kq = (c & 3) * 4;
            Bs[s][(kq + 0) * BSTR + r] = pb.x;
            Bs[s][(kq + 1) * BSTR + r] = pb.y;
            Bs[s][(kq + 2) * BSTR + r] = pb.z;
            Bs[s][(kq + 3) * BSTR + r] = pb.w;
        }
    };

    ull acc[8][2];
#pragma unroll
    for (int i = 0; i < 8; i++) { acc[i][0] = 0ull; acc[i][1] = 0ull; }

    ldg(0); sts(0); __syncthreads();
    const int nkt = (Kfull + BK - 1) / BK;
    for (int kt = 0; kt < nkt; kt++) {
        const int s = kt & 1;
        if (kt + 1 < nkt) ldg((kt + 1) * BK);
#pragma unroll
        for (int kk = 0; kk < BK; kk++) {
            const float4 a0 = *(const float4*)&As[s][kk * ASTR + ty * 8];
            const float4 a1 = *(const float4*)&As[s][kk * ASTR + ty * 8 + 4];
            const ulonglong2 bv = *(const ulonglong2*)&Bs[s][kk * BSTR + tx * 4];
            float av[8] = { a0.x, a0.y, a0.z, a0.w, a1.x, a1.y, a1.z, a1.w };
#pragma unroll
            for (int im = 0; im < 8; im++) {
                ull ad = pk2(av[im], av[im]);
                FMA2(acc[im][0], ad, bv.x);
                FMA2(acc[im][1], ad, bv.y);
            }
        }
        if (kt + 1 < nkt) sts(s ^ 1);
        __syncthreads();
    }

#pragma unroll
    for (int im = 0; im < 8; im++) {
        int m = m0 + ty * 8 + im;
        long ro = (long)m * 2048 + n0 + tx * 4;
        float v0, v1, v2, v3;
        upk2(acc[im][0], v0, v1);
        upk2(acc[im][1], v2, v3);
        if (bias) {
            v0 += bias[n0 + tx * 4 + 0]; v1 += bias[n0 + tx * 4 + 1];
            v2 += bias[n0 + tx * 4 + 2]; v3 += bias[n0 + tx * 4 + 3];
        }
        out[ro + 0] = v0; out[ro + 1] = v1; out[ro + 2] = v2; out[ro + 3] = v3;
    }
}

// broadcast video-final states [64,512] -> text-init [320,512]
__global__ void bc_init(const float* __restrict__ sh1, const float* __restrict__ sc1,
                        const float* __restrict__ sh2, const float* __restrict__ sc2,
                        float* __restrict__ dh1, float* __restrict__ dc1,
                        float* __restrict__ dh2, float* __restrict__ dc2)
{
    int idx = blockIdx.x * blockDim.x + threadIdx.x;
    if (idx >= 320 * 512) return;
    int q = idx >> 9, j = idx & 511;
    int s = (q / 5) * 512 + j;
    dh1[idx] = sh1[s]; dc1[idx] = sc1[s];
    dh2[idx] = sh2[s]; dc2[idx] = sc2[s];
}

// ---- decoder ----
__global__ __launch_bounds__(256)
void dec1_k(const float* __restrict__ A, const float* __restrict__ A2,
            const float* __restrict__ W, const float* __restrict__ bias,
            float* __restrict__ out)
{
    __shared__ float As[8][128];
    __shared__ float Bs[8][128];
    const int tid = threadIdx.x;
    const int r   = tid >> 1;
    const int kq  = (tid & 1) * 4;
    const int m0  = blockIdx.y * 128;
    const int n0  = blockIdx.x * 128;
    const int tx  = tid & 15;
    const int ty  = tid >> 4;
    const int m   = m0 + r;
    const int n   = n0 + r;

    float acc[8][8];
#pragma unroll
    for (int i = 0; i < 8; i++)
#pragma unroll
        for (int jj = 0; jj < 8; jj++) acc[i][jj] = 0.f;

    for (int kt = 0; kt < 128; kt++) {
        const int kb = kt * 8;
#pragma unroll
        for (int i = 0; i < 4; i++) {
            int k = kb + kq + i;
            As[kq + i][r] = (m < 320) ? ((k < 512) ? A[(long)m * 512 + k]
                                                   : A2[(long)m * 512 + (k - 512)]) : 0.f;
            Bs[kq + i][r] = W[(long)n * 1024 + k];
        }
        __syncthreads();
#pragma unroll
        for (int kk = 0; kk < 8; kk++) {
            float a[8], b[8];
#pragma unroll
            for (int i = 0; i < 8; i++) a[i] = As[kk][ty * 8 + i];
#pragma unroll
            for (int jj = 0; jj < 8; jj++) b[jj] = Bs[kk][tx * 8 + jj];
#pragma unroll
            for (int i = 0; i < 8; i++)
#pragma unroll
                for (int jj = 0; jj < 8; jj++) acc[i][jj] += a[i] * b[jj];
        }
        __syncthreads();
    }
#pragma unroll
    for (int i = 0; i < 8; i++) {
        int mm = m0 + ty * 8 + i;
        if (mm < 320) {
            long ro = (long)mm * 1024 + n0 + tx * 8;
#pragma unroll
            for (int jj = 0; jj < 8; jj++)
                out[ro + jj] = acc[i][jj] + bias[n0 + tx * 8 + jj];
        }
    }
}

__global__ void dec2_k(const float* __restrict__ fe, const float* __restrict__ w,
                       const float* __restrict__ b, float* __restrict__ out)
{
    int warp = (blockIdx.x * blockDim.x + threadIdx.x) >> 5;
    int lane = threadIdx.x & 31;
    if (warp >= 320) return;
    float s = 0.f;
    for (int k = lane; k < 1024; k += 32) s += fe[(long)warp * 1024 + k] * w[k];
#pragma unroll
    for (int o = 16; o; o >>= 1) s += __shfl_xor_sync(0xFFFFFFFFu, s, o);
    if (lane == 0) out[warp] = s + b[0];
}

__global__ void argmax_k(const float* __restrict__ outv, float* __restrict__ pred)
{
    int b = threadIdx.x;
    if (b < 64) {
        float best = outv[b * 5]; int bi = 0;
#pragma unroll
        for (int n = 1; n < 5; n++) {
            float v = outv[b * 5 + n];
            if (v > best) { best = v; bi = n; }
        }
        pred[b] = (float)bi;
    }
}

// ---------------- host orchestration ----------------
extern "C" void kernel_launch(void* const* d_in, const int* in_sizes, int n_in,
                              void* d_out, int out_size)
{
    const float* vf      = (const float*)d_in[0];
    const int*   ques    = (const int*)  d_in[1];
    const int*   qlen    = (const int*)  d_in[2];
    const float* embed   = (const float*)d_in[3];
    const float* Wih_t1  = (const float*)d_in[4];
    const float* Whh_t1  = (const float*)d_in[5];
    const float* b_t1    = (const float*)d_in[6];
    const float* Wih_t2  = (const float*)d_in[7];
    const float* Whh_t2  = (const float*)d_in[8];
    const float* b_t2    = (const float*)d_in[9];
    const float* Wih_v1  = (const float*)d_in[10];
    const float* Whh_v1  = (const float*)d_in[11];
    const float* b_v1    = (const float*)d_in[12];
    const float* Wih_v2  = (const float*)d_in[13];
    const float* Whh_v2  = (const float*)d_in[14];
    const float* b_v2    = (const float*)d_in[15];
    const float* dec1_w  = (const float*)d_in[16];
    const float* dec1_b  = (const float*)d_in[17];
    const float* dec2_w  = (const float*)d_in[18];
    const float* dec2_b  = (const float*)d_in[19];
    float* out = (float*)d_out;

    float *Xv1, *Xt1, *part, *vh1, *vc1, *vh2, *vc2;
    float *h1, *c1, *h2, *c2, *nh1, *nc1, *fe;
    cudaGetSymbolAddress((void**)&Xv1, g_Xv1);
    cudaGetSymbolAddress((void**)&Xt1, g_Xt1);
    cudaGetSymbolAddress((void**)&part, g_part);
    cudaGetSymbolAddress((void**)&vh1, g_vh1);
    cudaGetSymbolAddress((void**)&vc1, g_vc1);
    cudaGetSymbolAddress((void**)&vh2, g_vh2);
    cudaGetSymbolAddress((void**)&vc2, g_vc2);
    cudaGetSymbolAddress((void**)&h1,  g_h1);
    cudaGetSymbolAddress((void**)&c1,  g_c1);
    cudaGetSymbolAddress((void**)&h2,  g_h2);
    cudaGetSymbolAddress((void**)&c2,  g_c2);
    cudaGetSymbolAddress((void**)&nh1, g_nh1);
    cudaGetSymbolAddress((void**)&nc1, g_nc1);
    cudaGetSymbolAddress((void**)&fe,  g_fe);

    // zero video initial states
    cudaMemsetAsync(vh1, 0, 64 * 512 * sizeof(float));
    cudaMemsetAsync(vc1, 0, 64 * 512 * sizeof(float));
    cudaMemsetAsync(vh2, 0, 64 * 512 * sizeof(float));
    cudaMemsetAsync(vc2, 0, 64 * 512 * sizeof(float));

    // Xv1 = vf @ Wih_v1^T + b_v1 : [1280, 2048], K=8192
    sgemm3<0><<<dim3(32, 10), 256>>>(vf, Wih_v1, b_v1, Xv1, 8192, 8192,
                                     nullptr, nullptr);
    // Xt1 = emb @ Wih_t1^T + b_t1 : [6400, 2048], K=300 (gather)
    sgemm3<2><<<dim3(32, 50), 256>>>(nullptr, Wih_t1, b_t1, Xt1, 300, 300,
                                     ques, embed);

    // smem attributes for split-K cell GEMMs
    const int smem1 = (64 * 64 + 64 * 128) * 4;      // 48 KB
    const int smem2 = (64 * 128 + 128 * 128) * 4;    // 96 KB
    cudaFuncSetAttribute(vgemm<64, 0>, cudaFuncAttributeMaxDynamicSharedMemorySize, smem1);
    cudaFuncSetAttribute(vgemm<128, 1>, cudaFuncAttributeMaxDynamicSharedMemorySize, smem2);

    // ---- video recurrence: split-K GEMM + pointwise, in-place states ----
    for (int t = 0; t < 20; t++) {
        // cell1: gates = Xv1[m*20+t] + h1 @ Whh_v1^T   (K=512, 8 x 64-chunks)
        vgemm<64, 0><<<dim3(16, 8), 256, smem1>>>(vh1, nullptr, Whh_v1, nullptr, part);
        vpw<<<128, 256>>>(part, Xv1 + (long)t * 2048, 20 * 2048, nullptr, vh1, vc1);
        // cell2: gates = [h1new|h2] @ [Wih_v2|Whh_v2]^T + b_v2  (K=1024, 8 x 128)
        vgemm<128, 1><<<dim3(16, 8), 256, smem2>>>(vh1, vh2, Wih_v2, Whh_v2, part);
        vpw<<<128, 256>>>(part, nullptr, 0, b_v2, vh2, vc2);
    }

    // broadcast video-final states into text ping 0
    bc_init<<<640, 256>>>(vh1, vc1, vh2, vc2, h1, c1, h2, c2);

    // ---- text recurrence (M=320, masked): R3 fused cells, grid (16,5) ----
    int p = 0;
    for (int t = 0; t < 20; t++) {
        int q = p ^ 1;
        cell_k3<16, 16, 4, 2, 0, 1, 0, 0><<<dim3(16, 5), 256>>>(
            h1 + p * SS, nullptr, Whh_t1, nullptr, nullptr,
            Xt1 + (long)t * 320 * 2048, 2048,
            c1 + p * SS, nh1, nc1,
            nullptr, nullptr, nullptr, nullptr, nullptr, nullptr, 0);
        cell_k3<16, 16, 4, 2, 1, 0, 1, 1><<<dim3(16, 5), 256>>>(
            nh1, h2 + p * SS, Wih_t2, Whh_t2, b_t2,
            nullptr, 0,
            c2 + p * SS, h2 + q * SS, c2 + q * SS,
            nc1, h1 + p * SS, c1 + p * SS, h1 + q * SS, c1 + q * SS,
            qlen, t);
        p = q;
    }

    // ---- decoder ----  (final committed states in ping 0)
    dec1_k<<<dim3(8, 3), 256>>>(h1 + p * SS, h2 + p * SS, dec1_w, dec1_b, fe);
    dec2_k<<<10, 1024>>>(fe, dec2_w, dec2_b, out);
    if (out_size >= 384)
        argmax_k<<<1, 64>>>(out, out + 320);
}